// round 7
// baseline (speedup 1.0000x reference)
#include <cuda_runtime.h>
#include <math.h>
#include <stdint.h>

// Problem constants
#define B_ 1024
#define I_ 256
#define O_ 256
#define K_ 128

// Tiling
#define OT 32          // outputs per CTA (lane = o)
#define BT 256         // batches per CTA
#define NSEG 13        // i-segments; grid = 8*4*13 = 416 <= 444 = single wave at 3 CTAs/SM
#define ISEG_MAX 20
#define NW 16          // warps per CTA (512 threads)
#define BPW (BT / NW)  // 16 batches per warp
#define RS 129         // row stride (floats), odd -> gather bank (lane+l)%32 conflict-free

// Per-(b,i) packed activation data [i][b]:
//  .x = silu(tanh(x))  .y = 1-frac  .z = frac  .w = bitcast(l*4) byte offset into row
__device__ float4 g_pack[I_ * B_];
// Exclusive partial sums per i-segment (deterministic)
__device__ float g_part[NSEG][B_][O_];
// Arrival counters per (o-tile, b-group); reset by the reducing CTA each launch
__device__ int g_cnt[32];

__global__ __launch_bounds__(256) void prep_kernel(const float* __restrict__ x) {
    int idx = blockIdx.x * 256 + threadIdx.x;
    int b = idx / I_;
    int i = idx % I_;
    float xv = x[idx];
    float ax = fabsf(xv);
    float e  = __expf(-2.0f * ax);
    float r  = (1.0f - e) / (1.0f + e);
    float p  = copysignf(r, xv);                 // tanh(x) in [-1,1] => clip identity
    float sg = 1.0f / (1.0f + __expf(-p));
    float act = p * sg;                           // silu(p)
    float scaled = fminf(fmaxf((p + 1.0f) * 63.5f, 0.0f), 127.0f);
    int   l    = (int)scaled;                     // 0..127
    float frac = scaled - (float)l;
    g_pack[i * B_ + b] = make_float4(act, 1.0f - frac, frac, __int_as_float(l * 4));
}

__global__ __launch_bounds__(512, 3) void kan_main(
    const float* __restrict__ bw,     // [O, I]
    const float* __restrict__ coeff,  // [O, I, K]
    const float* __restrict__ scale,  // [O, I]
    const float* __restrict__ bias,   // [O]
    float* __restrict__ out)          // [B, O]
{
    __shared__ float sC[2][OT * RS];              // 33 KB: scaled rows + pad
    __shared__ __align__(16) float4 sPk[2][BT];   // 8 KB
    __shared__ float sW[ISEG_MAX][OT];            // 2.5 KB base weights for the segment
    __shared__ int sLast;

    const int tid  = threadIdx.x;
    const int lane = tid & 31;
    const int warp = tid >> 5;
    const int o0 = blockIdx.x * OT;
    const int b0 = blockIdx.y * BT;
    const int ibeg = (blockIdx.z * I_) / NSEG;          // variable-length segments (19 or 20)
    const int iend = ((blockIdx.z + 1) * I_) / NSEG;
    const int nIter = iend - ibeg;
    const int r0 = warp * 2;
    const int r1 = warp * 2 + 1;

    // One-time: base weights for the whole segment + zero row pads
    for (int t = tid; t < nIter * OT; t += 512) {
        int oo = t & 31, ii = t >> 5;
        sW[ii][oo] = bw[(size_t)(o0 + oo) * I_ + ibeg + ii];
    }
    if (tid < 64) sC[tid >> 5][(tid & 31) * RS + K_] = 0.0f;  // pad: l=127 reads it, frac=0

    float acc[BPW];
#pragma unroll
    for (int j = 0; j < BPW; j++) acc[j] = 0.0f;

    // Register prefetch buffers (R5-style staging: LDG -> regs -> STS, conflict-free)
    float va0[4], va1[4], sc0, sc1;
    float4 pkr;

    // Prologue: fetch iteration 0
    {
        const float* s0 = coeff + ((size_t)(o0 + r0) * I_ + ibeg) * (size_t)K_;
        const float* s1 = coeff + ((size_t)(o0 + r1) * I_ + ibeg) * (size_t)K_;
#pragma unroll
        for (int j = 0; j < 4; j++) { va0[j] = s0[lane + 32 * j]; va1[j] = s1[lane + 32 * j]; }
        sc0 = scale[(size_t)(o0 + r0) * I_ + ibeg];
        sc1 = scale[(size_t)(o0 + r1) * I_ + ibeg];
        if (tid < BT) pkr = g_pack[(size_t)ibeg * B_ + b0 + tid];
    }

    for (int it = 0; it < nIter; it++) {
        const int buf = it & 1;

        // STS phase: commit prefetched regs, scale folded here (conflict-free STS.32)
        {
            float* row0 = &sC[buf][r0 * RS];
            float* row1 = &sC[buf][r1 * RS];
#pragma unroll
            for (int j = 0; j < 4; j++) {
                row0[lane + 32 * j] = va0[j] * sc0;
                row1[lane + 32 * j] = va1[j] * sc1;
            }
            if (tid < BT) sPk[buf][tid] = pkr;
        }

        // Fetch phase: next iteration's LDGs (latency hidden behind hot loop)
        if (it + 1 < nIter) {
            const int inx = ibeg + it + 1;
            const float* s0 = coeff + ((size_t)(o0 + r0) * I_ + inx) * (size_t)K_;
            const float* s1 = coeff + ((size_t)(o0 + r1) * I_ + inx) * (size_t)K_;
#pragma unroll
            for (int j = 0; j < 4; j++) { va0[j] = s0[lane + 32 * j]; va1[j] = s1[lane + 32 * j]; }
            sc0 = scale[(size_t)(o0 + r0) * I_ + inx];
            sc1 = scale[(size_t)(o0 + r1) * I_ + inx];
            if (tid < BT) pkr = g_pack[(size_t)inx * B_ + b0 + tid];
        }

        __syncthreads();  // buffer 'buf' staged; prior buffer's readers all passed last barrier

        // Hot loop per (b,i): LDS.128 bcast + IADD + 2 conflict-free LDS.32 + 3 FFMA
        const float w = sW[it][lane];
        const char* rowb = (const char*)&sC[buf][lane * RS];
        const float4* pkp = &sPk[buf][warp * BPW];
#pragma unroll
        for (int bb = 0; bb < BPW; bb++) {
            float4 pk = pkp[bb];
            int off = __float_as_int(pk.w);
            float cl = *(const float*)(rowb + off);
            float cr = *(const float*)(rowb + off + 4);
            acc[bb] = fmaf(pk.y, cl, acc[bb]);   // (1-f) * c_l * s
            acc[bb] = fmaf(pk.z, cr, acc[bb]);   // f * c_r * s
            acc[bb] = fmaf(pk.x, w, acc[bb]);    // silu * base_weight
        }
    }

    // Exclusive partial slice (coalesced 128B rows)
#pragma unroll
    for (int bb = 0; bb < BPW; bb++)
        g_part[blockIdx.z][b0 + warp * BPW + bb][o0 + lane] = acc[bb];

    // Last-arriving CTA per (o-tile, b-group) reduces the NSEG partials (fixed order)
    __threadfence();
    __syncthreads();
    if (tid == 0) {
        int old = atomicAdd(&g_cnt[blockIdx.x * 4 + blockIdx.y], 1);
        sLast = (old == NSEG - 1);
    }
    __syncthreads();
    if (sLast) {
#pragma unroll
        for (int j = 0; j < (BT * OT) / 512; j++) {
            int e  = tid + 512 * j;
            int bl = e >> 5;
            int oo = e & 31;
            float sum = bias[o0 + oo];
#pragma unroll
            for (int sg = 0; sg < NSEG; sg++)
                sum += g_part[sg][b0 + bl][o0 + oo];
            out[(size_t)(b0 + bl) * O_ + o0 + oo] = sum;
        }
        if (tid == 0) g_cnt[blockIdx.x * 4 + blockIdx.y] = 0;  // re-arm for next replay
    }
}

extern "C" void kernel_launch(void* const* d_in, const int* in_sizes, int n_in,
                              void* d_out, int out_size) {
    const float* x     = (const float*)d_in[0];
    const float* bw    = (const float*)d_in[1];
    const float* coeff = (const float*)d_in[2];
    const float* scale = (const float*)d_in[3];
    const float* bias  = (const float*)d_in[4];
    float* out = (float*)d_out;

    prep_kernel<<<(B_ * I_) / 256, 256>>>(x);

    dim3 grid(O_ / OT, B_ / BT, NSEG);  // 8 x 4 x 13 = 416 CTAs = one wave at 3/SM
    kan_main<<<grid, 512>>>(bw, coeff, scale, bias, out);
}

// round 8
// speedup vs baseline: 1.4470x; 1.4470x over previous
#include <cuda_runtime.h>
#include <cuda_fp16.h>
#include <math.h>
#include <stdint.h>

// Problem constants
#define B_ 1024
#define I_ 256
#define O_ 256
#define K_ 128

// Tiling (R5 measured-best config)
#define OT 32          // outputs per CTA (lane = o)
#define BT 256         // batches per CTA
#define NSEG 16        // i-segments (grid.z)
#define ISEG (I_ / NSEG)
#define NW 16          // warps per CTA (512 threads)
#define BPW (BT / NW)  // 16 batches per warp
#define RS 129         // row stride in uint32 words; odd -> gather bank (lane+l)%32 conflict-free

// Per-(b,i) packed activation data [i][b], 8 bytes:
//  .x = half2(silu(tanh(x)), frac)   .y = l*4 (byte offset into pair row)
__device__ uint2 g_pk8[I_ * B_];
// Exclusive partial sums per i-segment (deterministic)
__device__ float g_part[NSEG][B_][O_];

__global__ __launch_bounds__(256) void prep_kernel(const float* __restrict__ x) {
    int idx = blockIdx.x * 256 + threadIdx.x;
    int b = idx / I_;
    int i = idx % I_;
    float xv = x[idx];
    float ax = fabsf(xv);
    float e  = __expf(-2.0f * ax);
    float r  = (1.0f - e) / (1.0f + e);
    float p  = copysignf(r, xv);                 // tanh(x) in [-1,1] => clip identity
    float sg = 1.0f / (1.0f + __expf(-p));
    float act = p * sg;                           // silu(p)
    float scaled = fminf(fmaxf((p + 1.0f) * 63.5f, 0.0f), 127.0f);
    int   l    = (int)scaled;                     // 0..127
    float frac = scaled - (float)l;
    __half2 h = __floats2half2_rn(act, frac);
    uint2 v;
    v.x = *reinterpret_cast<unsigned int*>(&h);
    v.y = (unsigned int)(l * 4);
    g_pk8[i * B_ + b] = v;
}

__global__ __launch_bounds__(512, 2) void kan_main(
    const float* __restrict__ bw,     // [O, I]
    const float* __restrict__ coeff,  // [O, I, K]
    const float* __restrict__ scale)  // [O, I]
{
    __shared__ unsigned int sC[2][OT * RS];       // 2 x 16.5 KB: fp16 pair rows (pad word unread)
    __shared__ __align__(16) uint2 sPk[2][BT];    // 2 x 2 KB
    __shared__ float sW[ISEG][OT];                // 2 KB base weights for the segment

    const int tid  = threadIdx.x;
    const int lane = tid & 31;
    const int warp = tid >> 5;
    const int o0 = blockIdx.x * OT;
    const int b0 = blockIdx.y * BT;
    const int i0 = blockIdx.z * ISEG;
    const int r0 = warp * 2;
    const int r1 = warp * 2 + 1;

    // One-time preload of base-weight slice
    for (int t = tid; t < ISEG * OT; t += 512) {
        int oo = t >> 4, ii = t & 15;
        sW[ii][oo] = bw[(size_t)(o0 + oo) * I_ + i0 + ii];
    }

    float acc[BPW];
#pragma unroll
    for (int j = 0; j < BPW; j++) acc[j] = 0.0f;

    // Register prefetch buffers: left taps a*, right taps b* (k+1, wrapped; safe since l=127 => frac=0)
    float a0[4], b0v[4], a1[4], b1v[4], sc0, sc1;
    uint2 pkr;

    // Prologue: fetch iteration 0
    {
        const float* s0 = coeff + ((size_t)(o0 + r0) * I_ + i0) * (size_t)K_;
        const float* s1 = coeff + ((size_t)(o0 + r1) * I_ + i0) * (size_t)K_;
#pragma unroll
        for (int j = 0; j < 4; j++) {
            int k = lane + 32 * j, k1 = (k + 1) & 127;
            a0[j] = s0[k]; b0v[j] = s0[k1];
            a1[j] = s1[k]; b1v[j] = s1[k1];
        }
        sc0 = scale[(size_t)(o0 + r0) * I_ + i0];
        sc1 = scale[(size_t)(o0 + r1) * I_ + i0];
        if (tid < BT) pkr = g_pk8[(size_t)i0 * B_ + b0 + tid];
    }

    for (int it = 0; it < ISEG; it++) {
        const int buf = it & 1;

        // STS phase: pack scaled fp16 pairs (conflict-free STS.32, banks (2r*129+lane+32j)%32 distinct per warp)
        {
            unsigned int* row0 = &sC[buf][r0 * RS];
            unsigned int* row1 = &sC[buf][r1 * RS];
#pragma unroll
            for (int j = 0; j < 4; j++) {
                __half2 p0 = __floats2half2_rn(a0[j] * sc0, b0v[j] * sc0);
                __half2 p1 = __floats2half2_rn(a1[j] * sc1, b1v[j] * sc1);
                row0[lane + 32 * j] = *reinterpret_cast<unsigned int*>(&p0);
                row1[lane + 32 * j] = *reinterpret_cast<unsigned int*>(&p1);
            }
            if (tid < BT) sPk[buf][tid] = pkr;
        }

        // Fetch phase: next iteration's LDGs (latency hidden behind hot loop)
        if (it + 1 < ISEG) {
            const int inx = i0 + it + 1;
            const float* s0 = coeff + ((size_t)(o0 + r0) * I_ + inx) * (size_t)K_;
            const float* s1 = coeff + ((size_t)(o0 + r1) * I_ + inx) * (size_t)K_;
#pragma unroll
            for (int j = 0; j < 4; j++) {
                int k = lane + 32 * j, k1 = (k + 1) & 127;
                a0[j] = s0[k]; b0v[j] = s0[k1];
                a1[j] = s1[k]; b1v[j] = s1[k1];
            }
            sc0 = scale[(size_t)(o0 + r0) * I_ + inx];
            sc1 = scale[(size_t)(o0 + r1) * I_ + inx];
            if (tid < BT) pkr = g_pk8[(size_t)inx * B_ + b0 + tid];
        }

        __syncthreads();  // buffer 'buf' staged; prior buffer's readers all passed last barrier

        // Hot loop: per 2 batches: 1 LDS.128 bcast + 2 conflict-free LDS.32 + cvt + 8 fp ops
        const float w = sW[it][lane];
        const char* rowb = (const char*)&sC[buf][lane * RS];
        const uint4* pkp = reinterpret_cast<const uint4*>(&sPk[buf][warp * BPW]);
#pragma unroll
        for (int bb2 = 0; bb2 < BPW / 2; bb2++) {
            uint4 two = pkp[bb2];
            // batch 0
            {
                float2 af = __half22float2(*reinterpret_cast<__half2*>(&two.x));  // (act, frac)
                unsigned int cw = *(const unsigned int*)(rowb + two.y);
                float2 c = __half22float2(*reinterpret_cast<__half2*>(&cw));      // (c_l, c_r)
                float sp = fmaf(af.y, c.y - c.x, c.x);   // c_l + f*(c_r - c_l)
                acc[2 * bb2]     += sp;
                acc[2 * bb2]      = fmaf(af.x, w, acc[2 * bb2]);
            }
            // batch 1
            {
                float2 af = __half22float2(*reinterpret_cast<__half2*>(&two.z));
                unsigned int cw = *(const unsigned int*)(rowb + two.w);
                float2 c = __half22float2(*reinterpret_cast<__half2*>(&cw));
                float sp = fmaf(af.y, c.y - c.x, c.x);
                acc[2 * bb2 + 1] += sp;
                acc[2 * bb2 + 1]  = fmaf(af.x, w, acc[2 * bb2 + 1]);
            }
        }
    }

    // Exclusive partial slice (coalesced 128B rows)
#pragma unroll
    for (int bb = 0; bb < BPW; bb++)
        g_part[blockIdx.z][b0 + warp * BPW + bb][o0 + lane] = acc[bb];
}

__global__ __launch_bounds__(256) void kan_reduce(
    const float* __restrict__ bias, float* __restrict__ out) {
    int t = blockIdx.x * 256 + threadIdx.x;  // one float4 of out each
    int b = t >> 6;
    int oq = t & 63;
    float4 s = reinterpret_cast<const float4*>(&g_part[0][b][0])[oq];
#pragma unroll
    for (int seg = 1; seg < NSEG; seg++) {
        float4 v = reinterpret_cast<const float4*>(&g_part[seg][b][0])[oq];
        s.x += v.x; s.y += v.y; s.z += v.z; s.w += v.w;
    }
    float4 bi = reinterpret_cast<const float4*>(bias)[oq];
    s.x += bi.x; s.y += bi.y; s.z += bi.z; s.w += bi.w;
    reinterpret_cast<float4*>(out)[t] = s;
}

extern "C" void kernel_launch(void* const* d_in, const int* in_sizes, int n_in,
                              void* d_out, int out_size) {
    const float* x     = (const float*)d_in[0];
    const float* bw    = (const float*)d_in[1];
    const float* coeff = (const float*)d_in[2];
    const float* scale = (const float*)d_in[3];
    const float* bias  = (const float*)d_in[4];
    float* out = (float*)d_out;

    prep_kernel<<<(B_ * I_) / 256, 256>>>(x);

    dim3 grid(O_ / OT, B_ / BT, NSEG);  // 8 x 4 x 16 = 512 CTAs
    kan_main<<<grid, 512>>>(bw, coeff, scale);

    kan_reduce<<<(B_ * O_ / 4) / 256, 256>>>(bias, out);
}